// round 1
// baseline (speedup 1.0000x reference)
#include <cuda_runtime.h>

#define S 64
#define P 2048
#define C 32
#define A 2048
#define D 128
#define E 64

#define SPLITS 2
#define PH (P / SPLITS)      // 1024 pixels per block
#define TILE 128
#define NTILES (PH / TILE)   // 8
#define NWARPS 8
#define NA 4
#define CAP (NWARPS * NA)    // 32 agents per pass

// Scratch (static __device__: no allocations allowed)
__device__ float g_att1[S * E * P];        // transposed: [s][e][p], 33.5 MB
__device__ float g_att2[A * E];
__device__ float g_pm[A * SPLITS];
__device__ float g_pl[A * SPLITS];
__device__ float g_pacc[A * SPLITS * C];

// ---------------------------------------------------------------------------
// Kernel 1a: att1[s,p,e] = b_sn[e] + sum_c gs[s,p,c] * W_sn[c,e]
// stored transposed as g_att1[s][e][p] so the attention kernel's tile loads
// are coalesced along p and SMEM reads are conflict-free.
// ---------------------------------------------------------------------------
__global__ __launch_bounds__(256) void k_att1(const float* __restrict__ gs,
                                              const float* __restrict__ Wsn,
                                              const float* __restrict__ bsn) {
    __shared__ float Ws[C * E];
    __shared__ float bs[E];
    int tid = threadIdx.x;
    for (int i = tid; i < C * E; i += blockDim.x) Ws[i] = Wsn[i];
    if (tid < E) bs[tid] = bsn[tid];
    __syncthreads();

    int row = blockIdx.x * blockDim.x + tid;   // row = s*P + p
    if (row >= S * P) return;
    int s = row / P, p = row % P;

    float g[C];
    const float4* gsr = reinterpret_cast<const float4*>(gs + (size_t)row * C);
#pragma unroll
    for (int j = 0; j < C / 4; j++) {
        float4 v = gsr[j];
        g[4 * j] = v.x; g[4 * j + 1] = v.y; g[4 * j + 2] = v.z; g[4 * j + 3] = v.w;
    }

    float* outb = g_att1 + (size_t)(s * E) * P + p;
    for (int e4 = 0; e4 < E; e4 += 4) {
        float ax = bs[e4], ay = bs[e4 + 1], az = bs[e4 + 2], aw = bs[e4 + 3];
#pragma unroll
        for (int c = 0; c < C; c++) {
            float4 w = *reinterpret_cast<const float4*>(&Ws[c * E + e4]);
            ax += g[c] * w.x; ay += g[c] * w.y; az += g[c] * w.z; aw += g[c] * w.w;
        }
        outb[(e4 + 0) * P] = ax;
        outb[(e4 + 1) * P] = ay;
        outb[(e4 + 2) * P] = az;
        outb[(e4 + 3) * P] = aw;
    }
}

// ---------------------------------------------------------------------------
// Kernel 1b: att2[a,e] = b_df[e] + sum_c dyn[a,c] * W_df[c,e]
// ---------------------------------------------------------------------------
__global__ __launch_bounds__(256) void k_att2(const float* __restrict__ dyn,
                                              const float* __restrict__ Wdf,
                                              const float* __restrict__ bdf) {
    __shared__ float Ws[D * E];   // 32 KB
    int tid = threadIdx.x;
    for (int i = tid; i < D * E; i += blockDim.x) Ws[i] = Wdf[i];
    __syncthreads();

    int idx = blockIdx.x * blockDim.x + tid;
    if (idx >= A * E) return;
    int a = idx >> 6, e = idx & 63;
    float acc = bdf[e];
    const float* dr = dyn + (size_t)a * D;
#pragma unroll 8
    for (int c = 0; c < D; c++) acc += dr[c] * Ws[c * E + e];
    g_att2[idx] = acc;
}

// ---------------------------------------------------------------------------
// Kernel 2: fused flash-style attention pool, grouped by scene.
// Block (s, half): all agents with scene_idx==s over pixels [half*1024, +1024).
// Each warp owns NA=4 agents; online softmax state in registers (lane=channel
// for the V accumulator, C=32 matches warp width exactly).
// b_fc is dropped: additive constant cancels in softmax.
// ---------------------------------------------------------------------------
__global__ __launch_bounds__(256) void k_attn(const int* __restrict__ sidx,
                                              const float* __restrict__ gs,
                                              const float* __restrict__ wfc) {
    extern __shared__ float sm[];
    float* att1_s = sm;                               // [E][TILE]  = 8192 f
    float* gs_s   = att1_s + E * TILE;                // [TILE][C]  = 4096 f
    float* att2_s = gs_s + TILE * C;                  // [CAP][E]   = 2048 f
    float* wfc_s  = att2_s + CAP * E;                 // 64 f
    float* wexp_s = wfc_s + E;                        // [CAP][32]  = 1024 f
    int*   alist  = (int*)(wexp_s + CAP * 32);        // up to A ints
    __shared__ int nA_sh;

    int tid = threadIdx.x;
    int wid = tid >> 5, lane = tid & 31;
    int sblk = blockIdx.x >> 1;
    int half = blockIdx.x & 1;
    int p0 = half * PH;

    if (tid == 0) nA_sh = 0;
    if (tid < E) wfc_s[tid] = wfc[tid];
    __syncthreads();
    for (int a = tid; a < A; a += blockDim.x)
        if (sidx[a] == sblk) alist[atomicAdd(&nA_sh, 1)] = a;
    __syncthreads();
    int nA = nA_sh;

    for (int g0 = 0; g0 < nA; g0 += CAP) {
        int ai[NA]; bool valid[NA];
#pragma unroll
        for (int i = 0; i < NA; i++) {
            int idx = g0 + wid * NA + i;
            valid[i] = (idx < nA);
            ai[i] = alist[valid[i] ? idx : 0];
        }
        // stage this warp's att2 rows into its private SMEM slots
#pragma unroll
        for (int i = 0; i < NA; i++) {
            att2_s[(wid * NA + i) * E + lane]      = g_att2[ai[i] * E + lane];
            att2_s[(wid * NA + i) * E + lane + 32] = g_att2[ai[i] * E + lane + 32];
        }
        __syncwarp();

        float m[NA], l[NA], accv[NA];
#pragma unroll
        for (int i = 0; i < NA; i++) { m[i] = -1e30f; l[i] = 0.f; accv[i] = 0.f; }

        for (int t = 0; t < NTILES; t++) {
            __syncthreads();
            // load att1 tile (already transposed [e][p] in gmem → direct copy)
            {
                const float* src = g_att1 + (size_t)(sblk * E) * P + p0 + t * TILE;
                for (int r = tid; r < E * (TILE / 4); r += blockDim.x) {
                    int e = r >> 5;
                    int j = r & 31;
                    reinterpret_cast<float4*>(att1_s + e * TILE)[j] =
                        reinterpret_cast<const float4*>(src + (size_t)e * P)[j];
                }
                const float4* gsrc = reinterpret_cast<const float4*>(
                    gs + (size_t)(sblk * P + p0 + t * TILE) * C);
                float4* gdst = reinterpret_cast<float4*>(gs_s);
                for (int r = tid; r < TILE * C / 4; r += blockDim.x) gdst[r] = gsrc[r];
            }
            __syncthreads();

#pragma unroll 1
            for (int sub = 0; sub < TILE / 32; sub++) {
                int pl = sub * 32 + lane;   // lane = pixel within tile
                float logit[NA] = {0.f, 0.f, 0.f, 0.f};
#pragma unroll
                for (int e4 = 0; e4 < E; e4 += 4) {
                    float4 w4 = *reinterpret_cast<const float4*>(wfc_s + e4);
                    float a0 = att1_s[(e4 + 0) * TILE + pl];
                    float a1 = att1_s[(e4 + 1) * TILE + pl];
                    float a2 = att1_s[(e4 + 2) * TILE + pl];
                    float a3 = att1_s[(e4 + 3) * TILE + pl];
#pragma unroll
                    for (int i = 0; i < NA; i++) {
                        float4 b = *reinterpret_cast<const float4*>(
                            att2_s + (wid * NA + i) * E + e4);
                        logit[i] += fmaxf(a0 + b.x, 0.f) * w4.x;
                        logit[i] += fmaxf(a1 + b.y, 0.f) * w4.y;
                        logit[i] += fmaxf(a2 + b.z, 0.f) * w4.z;
                        logit[i] += fmaxf(a3 + b.w, 0.f) * w4.w;
                    }
                }
                // online softmax update per agent
#pragma unroll
                for (int i = 0; i < NA; i++) {
                    float tm = logit[i];
#pragma unroll
                    for (int o = 16; o > 0; o >>= 1)
                        tm = fmaxf(tm, __shfl_xor_sync(0xffffffffu, tm, o));
                    float mn = fmaxf(m[i], tm);
                    float sc = __expf(m[i] - mn);
                    float w  = __expf(logit[i] - mn);
                    float ws = w;
#pragma unroll
                    for (int o = 16; o > 0; o >>= 1)
                        ws += __shfl_xor_sync(0xffffffffu, ws, o);
                    l[i] = l[i] * sc + ws;
                    m[i] = mn;
                    accv[i] *= sc;
                    wexp_s[(wid * NA + i) * 32 + lane] = w;
                }
                __syncwarp();
                // V accumulation: lane = channel, loop pixels of this sub
#pragma unroll
                for (int p4 = 0; p4 < 32; p4 += 4) {
                    float g0v = gs_s[(sub * 32 + p4 + 0) * C + lane];
                    float g1v = gs_s[(sub * 32 + p4 + 1) * C + lane];
                    float g2v = gs_s[(sub * 32 + p4 + 2) * C + lane];
                    float g3v = gs_s[(sub * 32 + p4 + 3) * C + lane];
#pragma unroll
                    for (int i = 0; i < NA; i++) {
                        float4 w = *reinterpret_cast<const float4*>(
                            wexp_s + (wid * NA + i) * 32 + p4);
                        accv[i] += w.x * g0v + w.y * g1v + w.z * g2v + w.w * g3v;
                    }
                }
                __syncwarp();
            }
        }
        // write partials for the combine kernel
#pragma unroll
        for (int i = 0; i < NA; i++) {
            if (valid[i]) {
                int a = ai[i];
                g_pacc[(a * SPLITS + half) * C + lane] = accv[i];
                if (lane == 0) {
                    g_pm[a * SPLITS + half] = m[i];
                    g_pl[a * SPLITS + half] = l[i];
                }
            }
        }
    }
}

// ---------------------------------------------------------------------------
// Kernel 3: combine the SPLITS partial softmax states per agent.
// ---------------------------------------------------------------------------
__global__ __launch_bounds__(256) void k_combine(float* __restrict__ out) {
    int gwarp = (blockIdx.x * blockDim.x + threadIdx.x) >> 5;
    int lane = threadIdx.x & 31;
    if (gwarp >= A) return;
    int a = gwarp;
    float m0 = g_pm[a * 2], m1 = g_pm[a * 2 + 1];
    float l0 = g_pl[a * 2], l1 = g_pl[a * 2 + 1];
    float M = fmaxf(m0, m1);
    float s0 = __expf(m0 - M), s1 = __expf(m1 - M);
    float L = l0 * s0 + l1 * s1;
    float v = (g_pacc[(a * 2) * C + lane] * s0 +
               g_pacc[(a * 2 + 1) * C + lane] * s1) / L;
    out[a * C + lane] = v;
}

// ---------------------------------------------------------------------------
extern "C" void kernel_launch(void* const* d_in, const int* in_sizes, int n_in,
                              void* d_out, int out_size) {
    const float* gs   = (const float*)d_in[0];   // global_scene [S,P,C]
    const int*   sidx = (const int*)d_in[1];     // scene_idx [A]
    const float* dyn  = (const float*)d_in[2];   // dynamic_encoding [A,D]
    const float* Wsn  = (const float*)d_in[3];   // [C,E]
    const float* bsn  = (const float*)d_in[4];   // [E]
    const float* Wdf  = (const float*)d_in[5];   // [D,E]
    const float* bdf  = (const float*)d_in[6];   // [E]
    const float* wfc  = (const float*)d_in[7];   // [E]
    // d_in[8] = b_fc: additive constant inside softmax — cancels; unused.
    float* out = (float*)d_out;

    k_att1<<<(S * P) / 256, 256>>>(gs, Wsn, bsn);
    k_att2<<<(A * E) / 256, 256>>>(dyn, Wdf, bdf);

    size_t smem = (size_t)(E * TILE + TILE * C + CAP * E + E + CAP * 32) * 4
                + (size_t)A * 4;
    cudaFuncSetAttribute(k_attn, cudaFuncAttributeMaxDynamicSharedMemorySize,
                         (int)smem);
    k_attn<<<S * SPLITS, 256, smem>>>(sidx, gs, wfc);

    k_combine<<<(A * 32) / 256, 256>>>(out);
}

// round 2
// speedup vs baseline: 1.7407x; 1.7407x over previous
#include <cuda_runtime.h>

#define S 64
#define P 2048
#define C 32
#define A 2048
#define D 128
#define E 64
#define E2 32            // E/2 packed pairs

#define SPLITS 2
#define PH (P / SPLITS)  // 1024
#define TILE 128
#define NTILES (PH / TILE)

typedef unsigned long long ull;

// packed f32x2 helpers (sm_100+)
__device__ __forceinline__ ull pack2(float lo, float hi) {
    ull r; asm("mov.b64 %0,{%1,%2};" : "=l"(r) : "f"(lo), "f"(hi)); return r;
}
__device__ __forceinline__ void unpack2(ull v, float& lo, float& hi) {
    asm("mov.b64 {%0,%1},%2;" : "=f"(lo), "=f"(hi) : "l"(v));
}
__device__ __forceinline__ ull fma2(ull a, ull b, ull c) {
    ull d; asm("fma.rn.f32x2 %0,%1,%2,%3;" : "=l"(d) : "l"(a), "l"(b), "l"(c)); return d;
}
__device__ __forceinline__ ull add2(ull a, ull b) {
    ull d; asm("add.rn.f32x2 %0,%1,%2;" : "=l"(d) : "l"(a), "l"(b)); return d;
}
__device__ __forceinline__ ull mul2(ull a, ull b) {
    ull d; asm("mul.rn.f32x2 %0,%1,%2;" : "=l"(d) : "l"(a), "l"(b)); return d;
}
__device__ __forceinline__ ull relu2(ull v) {
    float lo, hi; unpack2(v, lo, hi);
    return pack2(fmaxf(lo, 0.f), fmaxf(hi, 0.f));
}

// scratch (no allocations allowed)
__device__ float g_att2[A * E];
__device__ float g_pm[A * SPLITS];
__device__ float g_pl[A * SPLITS];
__device__ float g_pacc[A * SPLITS * C];

// ---------------------------------------------------------------------------
// att2[a,e] = b_df[e] + dyn[a,:] @ W_df[:,e]
// ---------------------------------------------------------------------------
__global__ __launch_bounds__(256) void k_att2(const float* __restrict__ dyn,
                                              const float* __restrict__ Wdf,
                                              const float* __restrict__ bdf) {
    __shared__ float Ws[D * E];
    int tid = threadIdx.x;
    for (int i = tid; i < D * E; i += blockDim.x) Ws[i] = Wdf[i];
    __syncthreads();
    int idx = blockIdx.x * blockDim.x + tid;
    if (idx >= A * E) return;
    int a = idx >> 6, e = idx & 63;
    float acc = bdf[e];
    const float* dr = dyn + (size_t)a * D;
#pragma unroll 8
    for (int c = 0; c < D; c++) acc += dr[c] * Ws[c * E + e];
    g_att2[idx] = acc;
}

// dynamic smem layout (bytes)
#define OFF_ATT1 0                         // ull[32*128]   32768
#define OFF_ATT2 32768                     // ull[64*32]    16384
#define OFF_WEXP 49152                     // ull[8*2*128]  16384
#define OFF_WSN  65536                     // ull[32*32]     8192
#define OFF_WFC  73728                     // ull[32]         256
#define OFF_BSN  73984                     // ull[32]         256
#define OFF_GST  74240                     // float[32*129] 16512
#define OFF_ALIST 90752                    // int[2048]      8192
#define SMEM_BYTES 98944

// process one chunk of 4 agents per warp (CH=0: slots 0..31, CH=1: 32..63)
template <int CH>
__device__ __forceinline__ void process_chunk(
    const ull* __restrict__ att1p, const ull* __restrict__ att2p,
    ull* __restrict__ wexp2w, const float* __restrict__ gs_sT,
    const ull* __restrict__ wfcp, int wid, int lane,
    float* m, float* l, ull* accp)
{
    const int base = CH * 32 + wid * 4;
    ull pl[16];
#pragma unroll
    for (int k = 0; k < 16; k++) pl[k] = 0ull;

#pragma unroll 4
    for (int e2 = 0; e2 < E2; e2++) {
        ull a0 = att1p[e2 * TILE + 0 * 32 + lane];
        ull a1 = att1p[e2 * TILE + 1 * 32 + lane];
        ull a2 = att1p[e2 * TILE + 2 * 32 + lane];
        ull a3 = att1p[e2 * TILE + 3 * 32 + lane];
        ull w2 = wfcp[e2];
#pragma unroll
        for (int i = 0; i < 4; i++) {
            ull b = att2p[(base + i) * E2 + e2];
            ull t0 = relu2(add2(a0, b));
            ull t1 = relu2(add2(a1, b));
            ull t2 = relu2(add2(a2, b));
            ull t3 = relu2(add2(a3, b));
            pl[i * 4 + 0] = fma2(t0, w2, pl[i * 4 + 0]);
            pl[i * 4 + 1] = fma2(t1, w2, pl[i * 4 + 1]);
            pl[i * 4 + 2] = fma2(t2, w2, pl[i * 4 + 2]);
            pl[i * 4 + 3] = fma2(t3, w2, pl[i * 4 + 3]);
        }
    }

    // per-tile online softmax update (one reduce per agent per tile)
    float w[4][4], sc[4];
#pragma unroll
    for (int i = 0; i < 4; i++) {
        float lw[4];
#pragma unroll
        for (int sub = 0; sub < 4; sub++) {
            float lo, hi; unpack2(pl[i * 4 + sub], lo, hi);
            lw[sub] = lo + hi;
        }
        float tm = fmaxf(fmaxf(lw[0], lw[1]), fmaxf(lw[2], lw[3]));
#pragma unroll
        for (int o = 16; o > 0; o >>= 1)
            tm = fmaxf(tm, __shfl_xor_sync(0xffffffffu, tm, o));
        float mo = m[CH * 4 + i];
        float mn = fmaxf(mo, tm);
        sc[i] = __expf(mo - mn);
        float ws = 0.f;
#pragma unroll
        for (int sub = 0; sub < 4; sub++) {
            w[i][sub] = __expf(lw[sub] - mn);
            ws += w[i][sub];
        }
#pragma unroll
        for (int o = 16; o > 0; o >>= 1)
            ws += __shfl_xor_sync(0xffffffffu, ws, o);
        l[CH * 4 + i] = l[CH * 4 + i] * sc[i] + ws;
        m[CH * 4 + i] = mn;
    }
    // rescale packed accumulators; stage exp weights as agent-pairs
#pragma unroll
    for (int pr = 0; pr < 2; pr++) {
        accp[CH * 2 + pr] = mul2(accp[CH * 2 + pr], pack2(sc[pr * 2], sc[pr * 2 + 1]));
#pragma unroll
        for (int sub = 0; sub < 4; sub++)
            wexp2w[pr * TILE + sub * 32 + lane] =
                pack2(w[pr * 2][sub], w[pr * 2 + 1][sub]);
    }
    __syncwarp();

    // V accumulation: lane = channel, packed over agent pairs
#pragma unroll 4
    for (int p = 0; p < TILE; p++) {
        float g = gs_sT[lane * 129 + p];
        ull gg = pack2(g, g);
        accp[CH * 2 + 0] = fma2(wexp2w[p], gg, accp[CH * 2 + 0]);
        accp[CH * 2 + 1] = fma2(wexp2w[TILE + p], gg, accp[CH * 2 + 1]);
    }
    __syncwarp();
}

// ---------------------------------------------------------------------------
// Fused: att1 tile compute + relu-add-dot logits + online softmax + V pooling
// Block = (scene, half). b_fc dropped (softmax-invariant).
// ---------------------------------------------------------------------------
__global__ __launch_bounds__(256) void k_attn(const int* __restrict__ sidx,
                                              const float* __restrict__ gs,
                                              const float* __restrict__ wfc,
                                              const float* __restrict__ Wsn,
                                              const float* __restrict__ bsn) {
    extern __shared__ char smraw[];
    ull*   att1p = (ull*)(smraw + OFF_ATT1);     // [E2][TILE]
    ull*   att2p = (ull*)(smraw + OFF_ATT2);     // [64][E2]
    ull*   wexp2 = (ull*)(smraw + OFF_WEXP);     // [8 warps][2][TILE]
    ull*   Wsnp  = (ull*)(smraw + OFF_WSN);      // [C][E2]
    ull*   wfcp  = (ull*)(smraw + OFF_WFC);      // [E2]
    ull*   bsnp  = (ull*)(smraw + OFF_BSN);      // [E2]
    float* gs_sT = (float*)(smraw + OFF_GST);    // [C][129]
    int*   alist = (int*)(smraw + OFF_ALIST);
    __shared__ int nA_sh;

    int tid = threadIdx.x;
    int wid = tid >> 5, lane = tid & 31;
    int sblk = blockIdx.x >> 1;
    int half = blockIdx.x & 1;
    int p0 = half * PH;

    if (tid == 0) nA_sh = 0;
    for (int i = tid; i < C * E; i += 256) ((float*)Wsnp)[i] = Wsn[i];
    if (tid < E) { ((float*)wfcp)[tid] = wfc[tid]; ((float*)bsnp)[tid] = bsn[tid]; }
    __syncthreads();
    for (int a = tid; a < A; a += 256)
        if (sidx[a] == sblk) alist[atomicAdd(&nA_sh, 1)] = a;
    __syncthreads();
    const int nA = nA_sh;
    if (nA == 0) return;

    const ull* g_att2u = (const ull*)g_att2;
    ull* wexp2w = wexp2 + wid * (2 * TILE);

    for (int g0 = 0; g0 < nA; g0 += 64) {
        __syncthreads();   // protect att2p from previous pass readers
        // stage att2 for up to 64 agent slots (clamped duplicates for pad)
        for (int idx = tid; idx < 64 * E2; idx += 256) {
            int j = idx >> 5, e2 = idx & 31;
            int src = g0 + j; if (src >= nA) src = nA - 1;
            att2p[idx] = g_att2u[(size_t)alist[src] * E2 + e2];
        }

        float m[8], l[8]; ull accp[4];
#pragma unroll
        for (int k = 0; k < 8; k++) { m[k] = -1e30f; l[k] = 0.f; }
#pragma unroll
        for (int k = 0; k < 4; k++) accp[k] = 0ull;
        const bool two = (nA - g0) > 32;

        for (int t = 0; t < NTILES; t++) {
            __syncthreads();   // tiles/att2p ready; previous readers done
            // load gs tile, transposed [c][p]
            {
                const float4* src = (const float4*)(gs + (size_t)(sblk * P + p0 + t * TILE) * C);
#pragma unroll
                for (int r = tid; r < TILE * 8; r += 256) {
                    int px = r >> 3, c4 = (r & 7) * 4;
                    float4 v = src[r];
                    gs_sT[(c4 + 0) * 129 + px] = v.x;
                    gs_sT[(c4 + 1) * 129 + px] = v.y;
                    gs_sT[(c4 + 2) * 129 + px] = v.z;
                    gs_sT[(c4 + 3) * 129 + px] = v.w;
                }
            }
            __syncthreads();
            // fused att1: att1p[e2][p] = bsn + sum_c gs[p][c] * Wsn[c][e-pair]
            {
                int p = tid & 127, eh = tid >> 7;   // eh: which 16 e-pairs
                ull acc[16];
#pragma unroll
                for (int e2 = 0; e2 < 16; e2++) acc[e2] = bsnp[eh * 16 + e2];
#pragma unroll 4
                for (int c = 0; c < C; c++) {
                    float gv = gs_sT[c * 129 + p];
                    ull gg = pack2(gv, gv);
#pragma unroll
                    for (int e2 = 0; e2 < 16; e2++)
                        acc[e2] = fma2(gg, Wsnp[c * E2 + eh * 16 + e2], acc[e2]);
                }
#pragma unroll
                for (int e2 = 0; e2 < 16; e2++)
                    att1p[(eh * 16 + e2) * TILE + p] = acc[e2];
            }
            __syncthreads();

            process_chunk<0>(att1p, att2p, wexp2w, gs_sT, wfcp, wid, lane, m, l, accp);
            if (two)
                process_chunk<1>(att1p, att2p, wexp2w, gs_sT, wfcp, wid, lane, m, l, accp);
        }

        // write partials
#pragma unroll
        for (int ch = 0; ch < 2; ch++) {
#pragma unroll
            for (int i = 0; i < 4; i++) {
                int idx = g0 + ch * 32 + wid * 4 + i;
                if (idx < nA) {
                    int a = alist[idx];
                    float lo, hi; unpack2(accp[ch * 2 + i / 2], lo, hi);
                    g_pacc[(size_t)(a * SPLITS + half) * C + lane] = (i & 1) ? hi : lo;
                    if (lane == 0) {
                        g_pm[a * SPLITS + half] = m[ch * 4 + i];
                        g_pl[a * SPLITS + half] = l[ch * 4 + i];
                    }
                }
            }
        }
    }
}

// ---------------------------------------------------------------------------
// combine the SPLITS partial softmax states per agent
// ---------------------------------------------------------------------------
__global__ __launch_bounds__(256) void k_combine(float* __restrict__ out) {
    int gwarp = (blockIdx.x * blockDim.x + threadIdx.x) >> 5;
    int lane = threadIdx.x & 31;
    if (gwarp >= A) return;
    int a = gwarp;
    float m0 = g_pm[a * 2], m1 = g_pm[a * 2 + 1];
    float l0 = g_pl[a * 2], l1 = g_pl[a * 2 + 1];
    float M = fmaxf(m0, m1);
    float s0 = __expf(m0 - M), s1 = __expf(m1 - M);
    float L = l0 * s0 + l1 * s1;
    out[a * C + lane] = (g_pacc[(size_t)(a * 2) * C + lane] * s0 +
                         g_pacc[(size_t)(a * 2 + 1) * C + lane] * s1) / L;
}

// ---------------------------------------------------------------------------
extern "C" void kernel_launch(void* const* d_in, const int* in_sizes, int n_in,
                              void* d_out, int out_size) {
    const float* gs   = (const float*)d_in[0];
    const int*   sidx = (const int*)d_in[1];
    const float* dyn  = (const float*)d_in[2];
    const float* Wsn  = (const float*)d_in[3];
    const float* bsn  = (const float*)d_in[4];
    const float* Wdf  = (const float*)d_in[5];
    const float* bdf  = (const float*)d_in[6];
    const float* wfc  = (const float*)d_in[7];
    float* out = (float*)d_out;

    k_att2<<<(A * E) / 256, 256>>>(dyn, Wdf, bdf);

    cudaFuncSetAttribute(k_attn, cudaFuncAttributeMaxDynamicSharedMemorySize,
                         SMEM_BYTES);
    k_attn<<<S * SPLITS, 256, SMEM_BYTES>>>(sidx, gs, wfc, Wsn, bsn);

    k_combine<<<(A * 32) / 256, 256>>>(out);
}